// round 1
// baseline (speedup 1.0000x reference)
#include <cuda_runtime.h>
#include <math.h>

#define NC 12
#define NPAIR 136
#define HID 128
#define MAXB 524288

// ---------------- scratch (static device globals; no allocs) ----------------
__device__ float  g_Wq[NPAIR * NC];            // packed quadratic-form weights [pair][12]
__device__ float  g_z[(size_t)MAXB * NC];      // z features [B][12]
__device__ double g_stats[90];                 // [0..11] sum z, [12..89] sum z_c z_d (c<=d)
__device__ float  g_W2[HID * NC];              // folded BN-affine weights
__device__ float  g_b2[HID];                   // folded BN-affine bias

// ---------------- kernel A: circuit simulation + weight build ----------------
__global__ void k_precompute(const float* __restrict__ p1,
                             const float* __restrict__ p2,
                             const float* __restrict__ p3) {
    __shared__ float SR[3 * 16 * 16];
    __shared__ float SI[3 * 16 * 16];
    int tid = threadIdx.x;

    if (tid < 90) g_stats[tid] = 0.0;   // zero accumulators every replay

    if (tid < 48) {
        int g   = tid >> 4;
        int col = tid & 15;
        const float* prm = (g == 0) ? p1 : (g == 1) ? p2 : p3;

        float sr[16], si[16];
        #pragma unroll
        for (int k = 0; k < 16; k++) { sr[k] = (k == col) ? 1.f : 0.f; si[k] = 0.f; }

        #pragma unroll
        for (int layer = 0; layer < 2; layer++) {
            // ---- H on all qubits ----
            #pragma unroll
            for (int q = 0; q < 4; q++) {
                int m = 1 << (3 - q);
                const float r = 0.70710678118654752f;
                #pragma unroll
                for (int k = 0; k < 16; k++) if (!(k & m)) {
                    int k1 = k | m;
                    float ar = sr[k], ai = si[k], br = sr[k1], bi = si[k1];
                    sr[k]  = r * (ar + br);  si[k]  = r * (ai + bi);
                    sr[k1] = r * (ar - br);  si[k1] = r * (ai - bi);
                }
            }
            // ---- RY, RZ, RX per qubit ----
            #pragma unroll
            for (int q = 0; q < 4; q++) {
                int m = 1 << (3 - q);
                float sy, cy; sincosf(0.5f * prm[layer * 12 + q], &sy, &cy);
                #pragma unroll
                for (int k = 0; k < 16; k++) if (!(k & m)) {
                    int k1 = k | m;
                    float ar = sr[k], ai = si[k], br = sr[k1], bi = si[k1];
                    sr[k]  = cy * ar - sy * br;  si[k]  = cy * ai - sy * bi;
                    sr[k1] = sy * ar + cy * br;  si[k1] = sy * ai + cy * bi;
                }
                float sz, cz; sincosf(0.5f * prm[layer * 12 + q + 4], &sz, &cz);
                #pragma unroll
                for (int k = 0; k < 16; k++) {
                    float re = sr[k], im = si[k];
                    if (!(k & m)) { sr[k] = re * cz + im * sz; si[k] = im * cz - re * sz; }
                    else          { sr[k] = re * cz - im * sz; si[k] = im * cz + re * sz; }
                }
                float sx, cx; sincosf(0.5f * prm[layer * 12 + q + 8], &sx, &cx);
                #pragma unroll
                for (int k = 0; k < 16; k++) if (!(k & m)) {
                    int k1 = k | m;
                    float ar = sr[k], ai = si[k], br = sr[k1], bi = si[k1];
                    sr[k]  = cx * ar + sx * bi;   si[k]  = cx * ai - sx * br;
                    sr[k1] = sx * ai + cx * br;   si[k1] = cx * bi - sx * ar;
                }
            }
            // ---- S on all qubits ----
            #pragma unroll
            for (int q = 0; q < 4; q++) {
                int m = 1 << (3 - q);
                #pragma unroll
                for (int k = 0; k < 16; k++) if (k & m) {
                    float t = sr[k]; sr[k] = -si[k]; si[k] = t;
                }
            }
            // ---- entanglers: CNOT(i,i+1), CZ(i,i+1) ----
            #pragma unroll
            for (int i = 0; i < 3; i++) {
                int m1 = 1 << (3 - i), m2 = 1 << (2 - i);
                #pragma unroll
                for (int k = 0; k < 16; k++) if ((k & m1) && !(k & m2)) {
                    int k1 = k | m2;
                    float tr = sr[k], ti = si[k];
                    sr[k] = sr[k1]; si[k] = si[k1];
                    sr[k1] = tr;    si[k1] = ti;
                }
                #pragma unroll
                for (int k = 0; k < 16; k++) if ((k & m1) && (k & m2)) {
                    sr[k] = -sr[k]; si[k] = -si[k];
                }
            }
            // ---- CNOT(3,0), CZ(3,0) ----
            {
                int m1 = 1, m2 = 8;
                #pragma unroll
                for (int k = 0; k < 16; k++) if ((k & m1) && !(k & m2)) {
                    int k1 = k | m2;
                    float tr = sr[k], ti = si[k];
                    sr[k] = sr[k1]; si[k] = si[k1];
                    sr[k1] = tr;    si[k1] = ti;
                }
                #pragma unroll
                for (int k = 0; k < 16; k++) if ((k & m1) && (k & m2)) {
                    sr[k] = -sr[k]; si[k] = -si[k];
                }
            }
        }
        #pragma unroll
        for (int k = 0; k < 16; k++) {
            SR[g * 256 + k * 16 + col] = sr[k];
            SI[g * 256 + k * 16 + col] = si[k];
        }
    }
    __syncthreads();

    // Build Wq[pair][c]: M_c[a][b] = sum_k sign_i(k) * Re(conj(U[k,a]) U[k,b])
    for (int e = tid; e < NPAIR * NC; e += blockDim.x) {
        int p = e / NC, c = e % NC;
        int a = 0, rem = p, cnt = 16;
        while (rem >= cnt) { rem -= cnt; a++; cnt--; }
        int b = a + rem;
        int g = c >> 2, i = c & 3;
        int bitpos = 3 - i;
        const float* sre = SR + g * 256;
        const float* sim = SI + g * 256;
        float sum = 0.f;
        #pragma unroll
        for (int k = 0; k < 16; k++) {
            float v = sre[k * 16 + a] * sre[k * 16 + b] + sim[k * 16 + a] * sim[k * 16 + b];
            sum += ((k >> bitpos) & 1) ? -v : v;
        }
        g_Wq[p * NC + c] = (a == b) ? sum : 2.f * sum;
    }
}

// ---------------- kernel B: z features (12 quadratic forms per sample) -------
__global__ __launch_bounds__(256) void k_pass1(const float* __restrict__ x, int B) {
    __shared__ float sW[NPAIR * NC];
    int tid = threadIdx.x;
    for (int i = tid; i < NPAIR * NC; i += 256) sW[i] = g_Wq[i];
    __syncthreads();

    int b = blockIdx.x * 256 + tid;
    if (b >= B) return;

    const float4* xp = reinterpret_cast<const float4*>(x + (size_t)b * 16);
    float4 v0 = xp[0], v1 = xp[1], v2 = xp[2], v3 = xp[3];
    float xv[16] = { v0.x, v0.y, v0.z, v0.w, v1.x, v1.y, v1.z, v1.w,
                     v2.x, v2.y, v2.z, v2.w, v3.x, v3.y, v3.z, v3.w };
    float s = 0.f;
    #pragma unroll
    for (int k = 0; k < 16; k++) s = fmaf(xv[k], xv[k], s);

    float4 A0 = {0, 0, 0, 0}, A1 = {0, 0, 0, 0}, A2 = {0, 0, 0, 0};
    int p = 0;
    #pragma unroll
    for (int a = 0; a < 16; a++) {
        #pragma unroll
        for (int bb = a; bb < 16; bb++) {
            float pr = xv[a] * xv[bb];
            const float4* w = reinterpret_cast<const float4*>(sW + p * NC);
            float4 w0 = w[0], w1 = w[1], w2 = w[2];
            A0.x = fmaf(w0.x, pr, A0.x); A0.y = fmaf(w0.y, pr, A0.y);
            A0.z = fmaf(w0.z, pr, A0.z); A0.w = fmaf(w0.w, pr, A0.w);
            A1.x = fmaf(w1.x, pr, A1.x); A1.y = fmaf(w1.y, pr, A1.y);
            A1.z = fmaf(w1.z, pr, A1.z); A1.w = fmaf(w1.w, pr, A1.w);
            A2.x = fmaf(w2.x, pr, A2.x); A2.y = fmaf(w2.y, pr, A2.y);
            A2.z = fmaf(w2.z, pr, A2.z); A2.w = fmaf(w2.w, pr, A2.w);
            p++;
        }
    }
    float inv = 1.0f / s;
    A0.x *= inv; A0.y *= inv; A0.z *= inv; A0.w *= inv;
    A1.x *= inv; A1.y *= inv; A1.z *= inv; A1.w *= inv;
    A2.x *= inv; A2.y *= inv; A2.z *= inv; A2.w *= inv;
    float4* zp = reinterpret_cast<float4*>(g_z + (size_t)b * NC);
    zp[0] = A0; zp[1] = A1; zp[2] = A2;
}

// ---------------- kernel B2: batch moments of z ------------------------------
__global__ __launch_bounds__(256) void k_stats(int B) {
    float s1[12], s2[78];
    #pragma unroll
    for (int c = 0; c < 12; c++) s1[c] = 0.f;
    #pragma unroll
    for (int i = 0; i < 78; i++) s2[i] = 0.f;

    for (int b = blockIdx.x * blockDim.x + threadIdx.x; b < B; b += gridDim.x * blockDim.x) {
        const float4* zp = reinterpret_cast<const float4*>(g_z + (size_t)b * NC);
        float4 a = zp[0], bq = zp[1], cq = zp[2];
        float z[12] = { a.x, a.y, a.z, a.w, bq.x, bq.y, bq.z, bq.w, cq.x, cq.y, cq.z, cq.w };
        #pragma unroll
        for (int c = 0; c < 12; c++) s1[c] += z[c];
        int idx = 0;
        #pragma unroll
        for (int c = 0; c < 12; c++)
            #pragma unroll
            for (int d = c; d < 12; d++)
                s2[idx++] = fmaf(z[c], z[d], s2[idx]);
    }

    #pragma unroll
    for (int off = 16; off; off >>= 1) {
        #pragma unroll
        for (int c = 0; c < 12; c++) s1[c] += __shfl_down_sync(0xFFFFFFFFu, s1[c], off);
        #pragma unroll
        for (int i = 0; i < 78; i++) s2[i] += __shfl_down_sync(0xFFFFFFFFu, s2[i], off);
    }

    __shared__ float red[8][90];
    int w = threadIdx.x >> 5, ln = threadIdx.x & 31;
    if (ln == 0) {
        #pragma unroll
        for (int c = 0; c < 12; c++) red[w][c] = s1[c];
        #pragma unroll
        for (int i = 0; i < 78; i++) red[w][12 + i] = s2[i];
    }
    __syncthreads();
    if (threadIdx.x < 90) {
        float t = 0.f;
        #pragma unroll
        for (int ww = 0; ww < 8; ww++) t += red[ww][threadIdx.x];
        atomicAdd(&g_stats[threadIdx.x], (double)t);
    }
}

// ---------------- kernel C: fold BN into 128x12 affine ------------------------
__global__ void k_fold(const float* __restrict__ fc_w,
                       const float* __restrict__ gamma,
                       const float* __restrict__ beta, int B) {
    __shared__ float zb[12], ez[78];
    int j = threadIdx.x;
    double invB = 1.0 / (double)B;
    if (j < 12) zb[j] = (float)(g_stats[j] * invB);
    if (j < 78) ez[j] = (float)(g_stats[12 + j] * invB);
    __syncthreads();

    float w[12];
    #pragma unroll
    for (int c = 0; c < 12; c++) w[c] = fc_w[j * 12 + c];

    double m1 = 0.0;
    #pragma unroll
    for (int c = 0; c < 12; c++) m1 += (double)w[c] * (double)zb[c];

    double m2 = 0.0;
    int idx = 0;
    #pragma unroll
    for (int c = 0; c < 12; c++)
        #pragma unroll
        for (int d = c; d < 12; d++) {
            double t = (double)w[c] * (double)w[d] * (double)ez[idx++];
            m2 += (c == d) ? t : 2.0 * t;
        }

    double var = m2 - m1 * m1;
    float rs = (float)(1.0 / sqrt(var + 1e-5));
    float sc = rs * gamma[j];
    #pragma unroll
    for (int c = 0; c < 12; c++) g_W2[j * 12 + c] = w[c] * sc;
    g_b2[j] = beta[j] - (float)m1 * sc;
}

// ---------------- kernel D: folded affine + ReLU -----------------------------
__global__ __launch_bounds__(256) void k_pass2(float* __restrict__ out, int B) {
    __shared__ float sz[256 * NC];
    int tid = threadIdx.x;
    int b0 = blockIdx.x * 256;

    int nsamp = B - b0; if (nsamp > 256) nsamp = 256;
    const float4* src = reinterpret_cast<const float4*>(g_z + (size_t)b0 * NC);
    float4* d4 = reinterpret_cast<float4*>(sz);
    int lim = nsamp * 3;
    for (int i = tid; i < lim; i += 256) d4[i] = src[i];

    int j = tid & 127, sub = tid >> 7;
    const float4* wv = reinterpret_cast<const float4*>(g_W2 + j * NC);
    float4 w0 = wv[0], w1 = wv[1], w2 = wv[2];
    float bias = g_b2[j];
    __syncthreads();

    for (int s = sub; s < nsamp; s += 2) {
        const float4* zp = reinterpret_cast<const float4*>(sz + s * NC);
        float4 a = zp[0], bq = zp[1], cq = zp[2];
        float h = bias;
        h = fmaf(w0.x, a.x, h);  h = fmaf(w0.y, a.y, h);
        h = fmaf(w0.z, a.z, h);  h = fmaf(w0.w, a.w, h);
        h = fmaf(w1.x, bq.x, h); h = fmaf(w1.y, bq.y, h);
        h = fmaf(w1.z, bq.z, h); h = fmaf(w1.w, bq.w, h);
        h = fmaf(w2.x, cq.x, h); h = fmaf(w2.y, cq.y, h);
        h = fmaf(w2.z, cq.z, h); h = fmaf(w2.w, cq.w, h);
        out[(size_t)(b0 + s) * HID + j] = fmaxf(h, 0.f);
    }
}

// ---------------- launch ------------------------------------------------------
extern "C" void kernel_launch(void* const* d_in, const int* in_sizes, int n_in,
                              void* d_out, int out_size) {
    const float* x  = (const float*)d_in[0];
    const float* p1 = (const float*)d_in[1];
    const float* p2 = (const float*)d_in[2];
    const float* p3 = (const float*)d_in[3];
    const float* fw = (const float*)d_in[4];
    // d_in[5] = fc_b (cancels inside BatchNorm), d_in[6] = gamma, d_in[7] = beta
    const float* gm = (const float*)d_in[6];
    const float* bt = (const float*)d_in[7];
    float* out = (float*)d_out;

    int B = in_sizes[0] / 16;
    int nb = (B + 255) / 256;

    k_precompute<<<1, 256>>>(p1, p2, p3);
    k_pass1<<<nb, 256>>>(x, B);
    k_stats<<<256, 256>>>(B);
    k_fold<<<1, 128>>>(fw, gm, bt, B);
    k_pass2<<<nb, 256>>>(out, B);
}

// round 2
// speedup vs baseline: 1.0898x; 1.0898x over previous
#include <cuda_runtime.h>
#include <math.h>

#define NC 12
#define HID 128
#define MAXB 524288

// ---------------- scratch (static device globals; no allocs) ----------------
__device__ __align__(16) float2 g_U[3 * 16 * 16];   // U[g][k][j] = (re, im)
__device__ float  g_z[(size_t)MAXB * NC];           // z features [B][12]
__device__ double g_stats[90];                      // [0..11] sum z, [12..89] sum z_c z_d (c<=d)

// ---------------- f32x2 packed helpers ----------------
__device__ __forceinline__ unsigned long long pk2(float a, float b) {
    unsigned long long r;
    asm("mov.b64 %0, {%1, %2};" : "=l"(r) : "f"(a), "f"(b));
    return r;
}
__device__ __forceinline__ void unpk2(unsigned long long v, float& a, float& b) {
    asm("mov.b64 {%0, %1}, %2;" : "=f"(a), "=f"(b) : "l"(v));
}
__device__ __forceinline__ unsigned long long ffma2(unsigned long long a,
                                                    unsigned long long b,
                                                    unsigned long long c) {
    unsigned long long d;
    asm("fma.rn.f32x2 %0, %1, %2, %3;" : "=l"(d) : "l"(a), "l"(b), "l"(c));
    return d;
}

// ---------------- kernel A: circuit simulation -> U matrices ----------------
__global__ void k_precompute(const float* __restrict__ p1,
                             const float* __restrict__ p2,
                             const float* __restrict__ p3) {
    int tid = threadIdx.x;
    if (tid < 90) g_stats[tid] = 0.0;   // zero accumulators every replay

    if (tid < 48) {
        int g   = tid >> 4;
        int col = tid & 15;
        const float* prm = (g == 0) ? p1 : (g == 1) ? p2 : p3;

        float sr[16], si[16];
        #pragma unroll
        for (int k = 0; k < 16; k++) { sr[k] = (k == col) ? 1.f : 0.f; si[k] = 0.f; }

        #pragma unroll
        for (int layer = 0; layer < 2; layer++) {
            // ---- H on all qubits ----
            #pragma unroll
            for (int q = 0; q < 4; q++) {
                int m = 1 << (3 - q);
                const float r = 0.70710678118654752f;
                #pragma unroll
                for (int k = 0; k < 16; k++) if (!(k & m)) {
                    int k1 = k | m;
                    float ar = sr[k], ai = si[k], br = sr[k1], bi = si[k1];
                    sr[k]  = r * (ar + br);  si[k]  = r * (ai + bi);
                    sr[k1] = r * (ar - br);  si[k1] = r * (ai - bi);
                }
            }
            // ---- RY, RZ, RX per qubit ----
            #pragma unroll
            for (int q = 0; q < 4; q++) {
                int m = 1 << (3 - q);
                float sy, cy; sincosf(0.5f * prm[layer * 12 + q], &sy, &cy);
                #pragma unroll
                for (int k = 0; k < 16; k++) if (!(k & m)) {
                    int k1 = k | m;
                    float ar = sr[k], ai = si[k], br = sr[k1], bi = si[k1];
                    sr[k]  = cy * ar - sy * br;  si[k]  = cy * ai - sy * bi;
                    sr[k1] = sy * ar + cy * br;  si[k1] = sy * ai + cy * bi;
                }
                float sz, cz; sincosf(0.5f * prm[layer * 12 + q + 4], &sz, &cz);
                #pragma unroll
                for (int k = 0; k < 16; k++) {
                    float re = sr[k], im = si[k];
                    if (!(k & m)) { sr[k] = re * cz + im * sz; si[k] = im * cz - re * sz; }
                    else          { sr[k] = re * cz - im * sz; si[k] = im * cz + re * sz; }
                }
                float sx, cx; sincosf(0.5f * prm[layer * 12 + q + 8], &sx, &cx);
                #pragma unroll
                for (int k = 0; k < 16; k++) if (!(k & m)) {
                    int k1 = k | m;
                    float ar = sr[k], ai = si[k], br = sr[k1], bi = si[k1];
                    sr[k]  = cx * ar + sx * bi;   si[k]  = cx * ai - sx * br;
                    sr[k1] = sx * ai + cx * br;   si[k1] = cx * bi - sx * ar;
                }
            }
            // ---- S on all qubits ----
            #pragma unroll
            for (int q = 0; q < 4; q++) {
                int m = 1 << (3 - q);
                #pragma unroll
                for (int k = 0; k < 16; k++) if (k & m) {
                    float t = sr[k]; sr[k] = -si[k]; si[k] = t;
                }
            }
            // ---- entanglers: CNOT(i,i+1), CZ(i,i+1) ----
            #pragma unroll
            for (int i = 0; i < 3; i++) {
                int m1 = 1 << (3 - i), m2 = 1 << (2 - i);
                #pragma unroll
                for (int k = 0; k < 16; k++) if ((k & m1) && !(k & m2)) {
                    int k1 = k | m2;
                    float tr = sr[k], ti = si[k];
                    sr[k] = sr[k1]; si[k] = si[k1];
                    sr[k1] = tr;    si[k1] = ti;
                }
                #pragma unroll
                for (int k = 0; k < 16; k++) if ((k & m1) && (k & m2)) {
                    sr[k] = -sr[k]; si[k] = -si[k];
                }
            }
            // ---- CNOT(3,0), CZ(3,0) ----
            {
                int m1 = 1, m2 = 8;
                #pragma unroll
                for (int k = 0; k < 16; k++) if ((k & m1) && !(k & m2)) {
                    int k1 = k | m2;
                    float tr = sr[k], ti = si[k];
                    sr[k] = sr[k1]; si[k] = si[k1];
                    sr[k1] = tr;    si[k1] = ti;
                }
                #pragma unroll
                for (int k = 0; k < 16; k++) if ((k & m1) && (k & m2)) {
                    sr[k] = -sr[k]; si[k] = -si[k];
                }
            }
        }
        #pragma unroll
        for (int k = 0; k < 16; k++) {
            g_U[g * 256 + k * 16 + col] = make_float2(sr[k], si[k]);
        }
    }
}

// ---------------- kernel B: z features via packed complex matvec -------------
__global__ __launch_bounds__(256) void k_pass1(const float* __restrict__ x, int B) {
    __shared__ __align__(16) float sU[1536];    // 3 * 16 * 16 * (re,im)
    int tid = threadIdx.x;
    {
        const float4* src = reinterpret_cast<const float4*>(g_U);
        float4* dst = reinterpret_cast<float4*>(sU);
        #pragma unroll
        for (int i = tid; i < 384; i += 256) dst[i] = src[i];
    }
    __syncthreads();

    int b = blockIdx.x * 256 + tid;
    if (b >= B) return;

    const float4* xp = reinterpret_cast<const float4*>(x + (size_t)b * 16);
    float4 v0 = xp[0], v1 = xp[1], v2 = xp[2], v3 = xp[3];
    float xv[16] = { v0.x, v0.y, v0.z, v0.w, v1.x, v1.y, v1.z, v1.w,
                     v2.x, v2.y, v2.z, v2.w, v3.x, v3.y, v3.z, v3.w };
    float s = 0.f;
    #pragma unroll
    for (int k = 0; k < 16; k++) s = fmaf(xv[k], xv[k], s);
    float inv = 1.0f / s;

    unsigned long long xd[16];
    #pragma unroll
    for (int j = 0; j < 16; j++) xd[j] = pk2(xv[j], xv[j]);

    #pragma unroll 1
    for (int g = 0; g < 3; g++) {
        float p[16];
        const double2* base = reinterpret_cast<const double2*>(sU + g * 512);
        #pragma unroll
        for (int k = 0; k < 16; k++) {
            const double2* row = base + k * 8;
            unsigned long long acc = 0ull;
            #pragma unroll
            for (int j2 = 0; j2 < 8; j2++) {
                double2 w = row[j2];
                acc = ffma2(__double_as_longlong(w.x), xd[2 * j2], acc);
                acc = ffma2(__double_as_longlong(w.y), xd[2 * j2 + 1], acc);
            }
            float re, im; unpk2(acc, re, im);
            p[k] = fmaf(re, re, im * im);
        }
        // Walsh partial sums -> 4 expectation values
        float a0[8], zq3 = 0.f;
        #pragma unroll
        for (int j = 0; j < 8; j++) {
            a0[j] = p[2 * j] + p[2 * j + 1];
            zq3  += p[2 * j] - p[2 * j + 1];
        }
        float a1[4], zq2 = 0.f;
        #pragma unroll
        for (int j = 0; j < 4; j++) {
            a1[j] = a0[2 * j] + a0[2 * j + 1];
            zq2  += a0[2 * j] - a0[2 * j + 1];
        }
        float zq1 = (a1[0] - a1[1]) + (a1[2] - a1[3]);
        float b2a = a1[0] + a1[1], b2b = a1[2] + a1[3];
        float zq0 = b2a - b2b;
        float4 zo = make_float4(zq0 * inv, zq1 * inv, zq2 * inv, zq3 * inv);
        reinterpret_cast<float4*>(g_z + (size_t)b * NC)[g] = zo;
    }
}

// ---------------- kernel C: batch moments of z ------------------------------
__global__ __launch_bounds__(256) void k_stats(int B) {
    float s1[12], s2[78];
    #pragma unroll
    for (int c = 0; c < 12; c++) s1[c] = 0.f;
    #pragma unroll
    for (int i = 0; i < 78; i++) s2[i] = 0.f;

    for (int b = blockIdx.x * blockDim.x + threadIdx.x; b < B; b += gridDim.x * blockDim.x) {
        const float4* zp = reinterpret_cast<const float4*>(g_z + (size_t)b * NC);
        float4 a = zp[0], bq = zp[1], cq = zp[2];
        float z[12] = { a.x, a.y, a.z, a.w, bq.x, bq.y, bq.z, bq.w, cq.x, cq.y, cq.z, cq.w };
        #pragma unroll
        for (int c = 0; c < 12; c++) s1[c] += z[c];
        int idx = 0;
        #pragma unroll
        for (int c = 0; c < 12; c++)
            #pragma unroll
            for (int d = c; d < 12; d++) {
                s2[idx] = fmaf(z[c], z[d], s2[idx]);
                idx++;
            }
    }

    #pragma unroll
    for (int off = 16; off; off >>= 1) {
        #pragma unroll
        for (int c = 0; c < 12; c++) s1[c] += __shfl_down_sync(0xFFFFFFFFu, s1[c], off);
        #pragma unroll
        for (int i = 0; i < 78; i++) s2[i] += __shfl_down_sync(0xFFFFFFFFu, s2[i], off);
    }

    __shared__ float red[8][90];
    int w = threadIdx.x >> 5, ln = threadIdx.x & 31;
    if (ln == 0) {
        #pragma unroll
        for (int c = 0; c < 12; c++) red[w][c] = s1[c];
        #pragma unroll
        for (int i = 0; i < 78; i++) red[w][12 + i] = s2[i];
    }
    __syncthreads();
    if (threadIdx.x < 90) {
        float t = 0.f;
        #pragma unroll
        for (int ww = 0; ww < 8; ww++) t += red[ww][threadIdx.x];
        atomicAdd(&g_stats[threadIdx.x], (double)t);
    }
}

// ---------------- kernel D: per-block BN fold + packed affine + ReLU ---------
#define P2_SAMP 512
__global__ __launch_bounds__(256) void k_pass2(float* __restrict__ out,
                                               const float* __restrict__ fc_w,
                                               const float* __restrict__ gm,
                                               const float* __restrict__ bt,
                                               int B) {
    __shared__ float zT[12][P2_SAMP + 2];     // transposed z tile (rows 8B-aligned)
    __shared__ float sW[HID * NC + HID];      // folded W2 [128][12] then b2 [128]
    __shared__ float sstat[90];
    int tid = threadIdx.x;

    if (tid < 90) sstat[tid] = (float)(g_stats[tid] / (double)B);
    __syncthreads();

    if (tid < HID) {
        int j = tid;
        float w[12];
        #pragma unroll
        for (int c = 0; c < 12; c++) w[c] = fc_w[j * 12 + c];
        float m1 = 0.f;
        #pragma unroll
        for (int c = 0; c < 12; c++) m1 = fmaf(w[c], sstat[c], m1);
        float m2 = 0.f;
        int idx = 0;
        #pragma unroll
        for (int c = 0; c < 12; c++)
            #pragma unroll
            for (int d = c; d < 12; d++) {
                float t = w[c] * w[d] * sstat[12 + idx];
                m2 += (c == d) ? t : 2.f * t;
                idx++;
            }
        float var = m2 - m1 * m1;
        float rs = 1.0f / sqrtf(var + 1e-5f);
        float sc = rs * gm[j];
        #pragma unroll
        for (int c = 0; c < 12; c++) sW[j * 12 + c] = w[c] * sc;
        sW[HID * NC + j] = bt[j] - m1 * sc;
    }

    int b0 = blockIdx.x * P2_SAMP;
    int nsamp = B - b0; if (nsamp > P2_SAMP) nsamp = P2_SAMP;

    // stage z transposed
    for (int s = tid; s < nsamp; s += 256) {
        const float4* zsrc = reinterpret_cast<const float4*>(g_z + (size_t)(b0 + s) * NC);
        float4 a = zsrc[0], b = zsrc[1], c = zsrc[2];
        zT[0][s] = a.x;  zT[1][s] = a.y;  zT[2][s] = a.z;  zT[3][s] = a.w;
        zT[4][s] = b.x;  zT[5][s] = b.y;  zT[6][s] = b.z;  zT[7][s] = b.w;
        zT[8][s] = c.x;  zT[9][s] = c.y;  zT[10][s] = c.z; zT[11][s] = c.w;
    }
    __syncthreads();

    int j = tid & 127;
    int sub = tid >> 7;
    unsigned long long wz[12];
    #pragma unroll
    for (int c = 0; c < 12; c++) wz[c] = pk2(sW[j * 12 + c], sW[j * 12 + c]);
    float bj = sW[HID * NC + j];
    unsigned long long bp = pk2(bj, bj);

    int npair = nsamp >> 1;
    for (int sp = sub; sp < npair; sp += 2) {
        unsigned long long acc = bp;
        #pragma unroll
        for (int c = 0; c < 12; c++) {
            unsigned long long zz = *reinterpret_cast<const unsigned long long*>(&zT[c][2 * sp]);
            acc = ffma2(wz[c], zz, acc);
        }
        float h0, h1; unpk2(acc, h0, h1);
        size_t s0 = (size_t)(b0 + 2 * sp);
        out[s0 * HID + j]       = fmaxf(h0, 0.f);
        out[(s0 + 1) * HID + j] = fmaxf(h1, 0.f);
    }
    if ((nsamp & 1) && sub == 0) {       // robustness for odd tails
        int s = nsamp - 1;
        float h = bj;
        #pragma unroll
        for (int c = 0; c < 12; c++) h = fmaf(sW[j * 12 + c], zT[c][s], h);
        out[(size_t)(b0 + s) * HID + j] = fmaxf(h, 0.f);
    }
}

// ---------------- launch ------------------------------------------------------
extern "C" void kernel_launch(void* const* d_in, const int* in_sizes, int n_in,
                              void* d_out, int out_size) {
    const float* x  = (const float*)d_in[0];
    const float* p1 = (const float*)d_in[1];
    const float* p2 = (const float*)d_in[2];
    const float* p3 = (const float*)d_in[3];
    const float* fw = (const float*)d_in[4];
    // d_in[5] = fc_b (cancels inside BatchNorm), d_in[6] = gamma, d_in[7] = beta
    const float* gm = (const float*)d_in[6];
    const float* bt = (const float*)d_in[7];
    float* out = (float*)d_out;

    int B = in_sizes[0] / 16;
    int nb1 = (B + 255) / 256;
    int nb2 = (B + P2_SAMP - 1) / P2_SAMP;

    k_precompute<<<1, 128>>>(p1, p2, p3);
    k_pass1<<<nb1, 256>>>(x, B);
    k_stats<<<256, 256>>>(B);
    k_pass2<<<nb2, 256>>>(out, fw, gm, bt, B);
}